// round 1
// baseline (speedup 1.0000x reference)
#include <cuda_runtime.h>
#include <math.h>

// ---------------- problem constants (fixed by setup_inputs) ----------------
#define Bsz   4
#define NTOK  13125            // 100*100 + 50*50 + 25*25
#define MTOT  (Bsz*NTOK)       // 52500
#define Dm    256
#define NHd   8
#define DHd   32
#define Lv    3
#define Pp    4
#define FFd   1024

// level geometry
__device__ __constant__ int   c_lvlH[3] = {100, 50, 25};
__device__ __constant__ int   c_lvlW[3] = {100, 50, 25};
__device__ __constant__ int   c_lvlN[3] = {10000, 2500, 625};
// offsets into d_val (floats): level l base; within level layout [B, Nl, D]
__device__ __constant__ size_t c_lvlOff[3] = {0, (size_t)Bsz*10000*Dm, (size_t)Bsz*10000*Dm + (size_t)Bsz*2500*Dm};

// ---------------- scratch (static device globals; no allocations) ----------
__device__ float d_val [ (size_t)MTOT * Dm ];     // projected values, 3 levels concat
__device__ float d_off [ (size_t)MTOT * 192 ];    // offsets  [tok, h*12+l*4+p, 2]
__device__ float d_attl[ (size_t)MTOT * 96  ];    // attn logits [tok, h*12+lp]
__device__ float d_ref [ (size_t)MTOT * 2   ];    // ref logits (sigmoid applied in sampler)
__device__ float d_bufA[ (size_t)MTOT * Dm ];     // sampled attention output (pre-Wo)
__device__ float d_bufB[ (size_t)MTOT * Dm ];     // Wo output / W2 output
__device__ float d_q   [ (size_t)MTOT * Dm ];     // post-LN1 activations
__device__ float d_h1  [ (size_t)MTOT * FFd ];    // FFN hidden

// ---------------- generic SGEMM: C[M,N] = A[M,K] @ W[K,N] + bias, optional GELU
// BM=BN=128, BK=8, 256 threads, 8x8 per-thread microtile. K must be %8.
template<int ACT>
__global__ __launch_bounds__(256)
void sgemm_bias(const float* __restrict__ A, const float* __restrict__ W,
                const float* __restrict__ bias, float* __restrict__ C,
                int M, int K, int N)
{
    __shared__ float As[8][128];
    __shared__ float Bs[8][128];

    const int tid = threadIdx.x;
    const int bm  = blockIdx.y * 128;
    const int bn  = blockIdx.x * 128;
    const int tr  = tid / 16;         // 0..15
    const int tc  = tid % 16;         // 0..15

    // load mapping
    const int aRow = tid >> 1;        // 0..127
    const int aCol = (tid & 1) * 4;   // 0 or 4
    const int bRow = tid >> 5;        // 0..7
    const int bCol = (tid & 31) * 4;  // 0..124

    float acc[8][8];
    #pragma unroll
    for (int i = 0; i < 8; i++)
        #pragma unroll
        for (int j = 0; j < 8; j++) acc[i][j] = 0.f;

    for (int k0 = 0; k0 < K; k0 += 8) {
        const int gm = bm + aRow;
        #pragma unroll
        for (int i = 0; i < 4; i++) {
            float v = 0.f;
            if (gm < M) v = A[(size_t)gm * K + (k0 + aCol + i)];
            As[aCol + i][aRow] = v;
        }
        #pragma unroll
        for (int i = 0; i < 4; i++) {
            const int gn = bn + bCol + i;
            float v = 0.f;
            if (gn < N) v = W[(size_t)(k0 + bRow) * N + gn];
            Bs[bRow][bCol + i] = v;
        }
        __syncthreads();

        #pragma unroll
        for (int k = 0; k < 8; k++) {
            float aF[8], bF[8];
            #pragma unroll
            for (int i = 0; i < 8; i++) aF[i] = As[k][tr * 8 + i];
            #pragma unroll
            for (int j = 0; j < 8; j++) bF[j] = Bs[k][tc * 8 + j];
            #pragma unroll
            for (int i = 0; i < 8; i++)
                #pragma unroll
                for (int j = 0; j < 8; j++)
                    acc[i][j] = fmaf(aF[i], bF[j], acc[i][j]);
        }
        __syncthreads();
    }

    #pragma unroll
    for (int i = 0; i < 8; i++) {
        const int gm = bm + tr * 8 + i;
        if (gm >= M) continue;
        #pragma unroll
        for (int j = 0; j < 8; j++) {
            const int gn = bn + tc * 8 + j;
            if (gn >= N) continue;
            float v = acc[i][j] + bias[gn];
            if (ACT == 1) v = 0.5f * v * (1.f + erff(v * 0.70710678118654752f));
            C[(size_t)gm * N + gn] = v;
        }
    }
}

// ---------------- reference-point projection: 2 outputs per token ----------
__global__ void ref_proj_kernel(const float* __restrict__ q,
                                const float* __restrict__ Wref,
                                const float* __restrict__ bref,
                                float* __restrict__ out)
{
    const int warp = (blockIdx.x * blockDim.x + threadIdx.x) >> 5;
    const int lane = threadIdx.x & 31;
    if (warp >= MTOT) return;
    const float* qr = q + (size_t)warp * Dm;
    float s0 = 0.f, s1 = 0.f;
    #pragma unroll
    for (int k = lane; k < Dm; k += 32) {
        const float qv = qr[k];
        s0 = fmaf(qv, Wref[k * 2 + 0], s0);
        s1 = fmaf(qv, Wref[k * 2 + 1], s1);
    }
    #pragma unroll
    for (int o = 16; o; o >>= 1) {
        s0 += __shfl_xor_sync(0xffffffffu, s0, o);
        s1 += __shfl_xor_sync(0xffffffffu, s1, o);
    }
    if (lane == 0) {
        out[(size_t)warp * 2 + 0] = s0 + bref[0];
        out[(size_t)warp * 2 + 1] = s1 + bref[1];
    }
}

// ---------------- fused softmax + sigmoid + bilinear sampling --------------
// one block (256 thr) per token; warp = head, lane = channel (DH=32)
__global__ __launch_bounds__(256)
void sample_kernel(float* __restrict__ out)
{
    const int t    = blockIdx.x;         // 0..MTOT-1
    const int b    = t / NTOK;
    const int tid  = threadIdx.x;
    const int h    = tid >> 5;
    const int lane = tid & 31;

    __shared__ float s_aw[96];
    __shared__ float s_x[96];
    __shared__ float s_y[96];

    const float refx = 1.f / (1.f + __expf(-d_ref[(size_t)t * 2 + 0]));
    const float refy = 1.f / (1.f + __expf(-d_ref[(size_t)t * 2 + 1]));

    if (tid < 96) {
        const int lp = tid % 12;
        const int l  = lp >> 2;
        const float ox = d_off[(size_t)t * 192 + tid * 2 + 0];
        const float oy = d_off[(size_t)t * 192 + tid * 2 + 1];
        const float Wl = (float)c_lvlW[l];
        const float Hl = (float)c_lvlH[l];
        s_x[tid]  = fmaf(refx, Wl, ox) - 0.5f;
        s_y[tid]  = fmaf(refy, Hl, oy) - 0.5f;
        s_aw[tid] = d_attl[(size_t)t * 96 + tid];
    }
    __syncthreads();

    if (tid < 8) {  // per-head softmax over 12 (l,p) combos
        float m = -1e30f;
        #pragma unroll
        for (int j = 0; j < 12; j++) m = fmaxf(m, s_aw[tid * 12 + j]);
        float s = 0.f;
        #pragma unroll
        for (int j = 0; j < 12; j++) { const float e = __expf(s_aw[tid * 12 + j] - m); s_aw[tid * 12 + j] = e; s += e; }
        const float inv = 1.f / s;
        #pragma unroll
        for (int j = 0; j < 12; j++) s_aw[tid * 12 + j] *= inv;
    }
    __syncthreads();

    float acc = 0.f;
    #pragma unroll
    for (int l = 0; l < Lv; l++) {
        const int   Hl = c_lvlH[l];
        const int   Wl = c_lvlW[l];
        const float* vl = d_val + c_lvlOff[l] + (size_t)b * c_lvlN[l] * Dm + (h * DHd + lane);
        #pragma unroll
        for (int p = 0; p < Pp; p++) {
            const int idx = h * 12 + l * 4 + p;
            const float x = s_x[idx], y = s_y[idx], w = s_aw[idx];
            const float x0f = floorf(x), y0f = floorf(y);
            const int   x0 = (int)x0f, y0 = (int)y0f;
            const float lx = x - x0f, ly = y - y0f;
            const float w00 = (1.f - lx) * (1.f - ly);
            const float w01 = lx * (1.f - ly);
            const float w10 = (1.f - lx) * ly;
            const float w11 = lx * ly;
            float v = 0.f;
            const bool xin0 = (x0 >= 0) & (x0 < Wl);
            const bool xin1 = (x0 + 1 >= 0) & (x0 + 1 < Wl);
            const bool yin0 = (y0 >= 0) & (y0 < Hl);
            const bool yin1 = (y0 + 1 >= 0) & (y0 + 1 < Hl);
            if (xin0 & yin0) v = fmaf(w00, vl[(size_t)(y0 * Wl + x0) * Dm], v);
            if (xin1 & yin0) v = fmaf(w01, vl[(size_t)(y0 * Wl + x0 + 1) * Dm], v);
            if (xin0 & yin1) v = fmaf(w10, vl[(size_t)((y0 + 1) * Wl + x0) * Dm], v);
            if (xin1 & yin1) v = fmaf(w11, vl[(size_t)((y0 + 1) * Wl + x0 + 1) * Dm], v);
            acc = fmaf(w, v, acc);
        }
    }
    out[(size_t)t * Dm + h * DHd + lane] = acc;
}

// ---------------- residual + LayerNorm (row = 256 elems, block = 256 thr) --
__global__ __launch_bounds__(256)
void ln_residual_kernel(const float* __restrict__ x, const float* __restrict__ y,
                        const float* __restrict__ g, const float* __restrict__ be,
                        float* __restrict__ out)
{
    const int t   = blockIdx.x;
    const int tid = threadIdx.x;
    const float v = x[(size_t)t * Dm + tid] + y[(size_t)t * Dm + tid];

    __shared__ float sh[18];
    float s = v, sq = v * v;
    #pragma unroll
    for (int o = 16; o; o >>= 1) {
        s  += __shfl_xor_sync(0xffffffffu, s,  o);
        sq += __shfl_xor_sync(0xffffffffu, sq, o);
    }
    const int w = tid >> 5, lane = tid & 31;
    if (lane == 0) { sh[w] = s; sh[w + 8] = sq; }
    __syncthreads();
    if (tid == 0) {
        float ts = 0.f, tq = 0.f;
        #pragma unroll
        for (int i = 0; i < 8; i++) { ts += sh[i]; tq += sh[i + 8]; }
        sh[16] = ts * (1.f / Dm);
        sh[17] = tq * (1.f / Dm);
    }
    __syncthreads();
    const float mean = sh[16];
    const float var  = fmaxf(sh[17] - mean * mean, 0.f);
    const float inv  = rsqrtf(var + 1e-5f);
    out[(size_t)t * Dm + tid] = (v - mean) * inv * g[tid] + be[tid];
}

// ---------------- host orchestration ---------------------------------------
static inline dim3 gemm_grid(int M, int N) { return dim3((N + 127) / 128, (M + 127) / 128); }

extern "C" void kernel_launch(void* const* d_in, const int* in_sizes, int n_in,
                              void* d_out, int out_size)
{
    const float* query = (const float*)d_in[0];
    const float* p3    = (const float*)d_in[1];
    const float* p4    = (const float*)d_in[2];
    const float* p5    = (const float*)d_in[3];
    const float* Wv    = (const float*)d_in[4];
    const float* bv    = (const float*)d_in[5];
    const float* Woff  = (const float*)d_in[6];
    const float* boff  = (const float*)d_in[7];
    const float* Wattn = (const float*)d_in[8];
    const float* battn = (const float*)d_in[9];
    const float* Wref  = (const float*)d_in[10];
    const float* bref  = (const float*)d_in[11];
    const float* Wo    = (const float*)d_in[12];
    const float* bo    = (const float*)d_in[13];
    const float* W1    = (const float*)d_in[14];
    const float* b1    = (const float*)d_in[15];
    const float* W2    = (const float*)d_in[16];
    const float* b2    = (const float*)d_in[17];
    const float* g1    = (const float*)d_in[18];
    const float* be1   = (const float*)d_in[19];
    const float* g2    = (const float*)d_in[20];
    const float* be2   = (const float*)d_in[21];
    float* out = (float*)d_out;

    float *val, *off, *attl, *ref, *bufA, *bufB, *q, *h1;
    cudaGetSymbolAddress((void**)&val,  d_val);
    cudaGetSymbolAddress((void**)&off,  d_off);
    cudaGetSymbolAddress((void**)&attl, d_attl);
    cudaGetSymbolAddress((void**)&ref,  d_ref);
    cudaGetSymbolAddress((void**)&bufA, d_bufA);
    cudaGetSymbolAddress((void**)&bufB, d_bufB);
    cudaGetSymbolAddress((void**)&q,    d_q);
    cudaGetSymbolAddress((void**)&h1,   d_h1);

    // 1. value projections per level (output laid out [B, Nl, D] at level offsets)
    sgemm_bias<0><<<gemm_grid(Bsz * 10000, Dm), 256>>>(p3, Wv, bv, val,                               Bsz * 10000, Dm, Dm);
    sgemm_bias<0><<<gemm_grid(Bsz * 2500,  Dm), 256>>>(p4, Wv, bv, val + (size_t)Bsz * 10000 * Dm,    Bsz * 2500,  Dm, Dm);
    sgemm_bias<0><<<gemm_grid(Bsz * 625,   Dm), 256>>>(p5, Wv, bv, val + (size_t)Bsz * 12500 * Dm,    Bsz * 625,   Dm, Dm);

    // 2. query projections
    sgemm_bias<0><<<gemm_grid(MTOT, 192), 256>>>(query, Woff,  boff,  off,  MTOT, Dm, 192);
    sgemm_bias<0><<<gemm_grid(MTOT, 96),  256>>>(query, Wattn, battn, attl, MTOT, Dm, 96);
    ref_proj_kernel<<<(MTOT * 32 + 255) / 256, 256>>>(query, Wref, bref, ref);

    // 3. fused softmax + sampling -> bufA (attention output before Wo)
    sample_kernel<<<MTOT, 256>>>(bufA);

    // 4. output projection + residual + LN1 -> q
    sgemm_bias<0><<<gemm_grid(MTOT, Dm), 256>>>(bufA, Wo, bo, bufB, MTOT, Dm, Dm);
    ln_residual_kernel<<<MTOT, 256>>>(query, bufB, g1, be1, q);

    // 5. FFN: gelu(q@W1+b1) @ W2 + b2, residual + LN2 -> out
    sgemm_bias<1><<<gemm_grid(MTOT, FFd), 256>>>(q, W1, b1, h1, MTOT, Dm, FFd);
    sgemm_bias<0><<<gemm_grid(MTOT, Dm),  256>>>(h1, W2, b2, bufB, MTOT, FFd, Dm);
    ln_residual_kernel<<<MTOT, 256>>>(q, bufB, g2, be2, out);
}

// round 3
// speedup vs baseline: 2.1597x; 2.1597x over previous
#include <cuda_runtime.h>
#include <cuda_bf16.h>
#include <math.h>
#include <cstdint>

// ---------------- problem constants ----------------
#define Bsz   4
#define NTOK  13125
#define MTOT  (Bsz*NTOK)      // 52500
#define Dm    256
#define NHd   8
#define DHd   32
#define FFd   1024
#define NQC   384             // fused q-proj width: 192 off | 96 attn | 2 ref | 94 pad

__device__ __constant__ int    c_lvlH[3] = {100, 50, 25};
__device__ __constant__ int    c_lvlW[3] = {100, 50, 25};
__device__ __constant__ int    c_lvlN[3] = {10000, 2500, 625};
__device__ __constant__ size_t c_lvlOff[3] = {0, (size_t)Bsz*10000*Dm,
                                              (size_t)Bsz*10000*Dm + (size_t)Bsz*2500*Dm};

// ---------------- scratch (__device__ globals; no allocations) ----------------
__device__ __align__(16) __nv_bfloat16 g_valin_h[(size_t)MTOT*Dm], g_valin_l[(size_t)MTOT*Dm];
__device__ __align__(16) float         g_val   [(size_t)MTOT*Dm];
__device__ __align__(16) __nv_bfloat16 g_qh    [(size_t)MTOT*Dm], g_ql[(size_t)MTOT*Dm];
__device__ __align__(16) float         g_qcat  [(size_t)MTOT*NQC];
__device__ __align__(16) __nv_bfloat16 g_sah   [(size_t)MTOT*Dm], g_sal[(size_t)MTOT*Dm];
__device__ __align__(16) float         g_bufB  [(size_t)MTOT*Dm];
__device__ __align__(16) float         g_q     [(size_t)MTOT*Dm];
__device__ __align__(16) __nv_bfloat16 g_qnh   [(size_t)MTOT*Dm], g_qnl[(size_t)MTOT*Dm];
__device__ __align__(16) __nv_bfloat16 g_h1h   [(size_t)MTOT*FFd], g_h1l[(size_t)MTOT*FFd];

__device__ __align__(16) __nv_bfloat16 g_WvT_h[Dm*Dm],   g_WvT_l[Dm*Dm];
__device__ __align__(16) __nv_bfloat16 g_WqT_h[NQC*Dm],  g_WqT_l[NQC*Dm];
__device__ __align__(16) __nv_bfloat16 g_WoT_h[Dm*Dm],   g_WoT_l[Dm*Dm];
__device__ __align__(16) __nv_bfloat16 g_W1T_h[FFd*Dm],  g_W1T_l[FFd*Dm];
__device__ __align__(16) __nv_bfloat16 g_W2T_h[Dm*FFd],  g_W2T_l[Dm*FFd];
__device__ float         g_bq[NQC];

// ---------------- baseline-PTX primitives (no sm_103a-only features) --------
__device__ __forceinline__ uint32_t smem_u32(const void* p) {
    uint32_t a;
    asm("{ .reg .u64 t; cvta.to.shared.u64 t, %1; cvt.u32.u64 %0, t; }" : "=r"(a) : "l"(p));
    return a;
}
__device__ __forceinline__ void cpa16(uint32_t dst, const void* src, int srcBytes) {
    asm volatile("cp.async.cg.shared.global [%0], [%1], 16, %2;"
                 :: "r"(dst), "l"(src), "r"(srcBytes) : "memory");
}
__device__ __forceinline__ void cpa_commit() {
    asm volatile("cp.async.commit_group;" ::: "memory");
}
template<int N> __device__ __forceinline__ void cpa_wait() {
    asm volatile("cp.async.wait_group %0;" :: "n"(N) : "memory");
}
__device__ __forceinline__ void ldm_x4(uint32_t& r0, uint32_t& r1, uint32_t& r2, uint32_t& r3,
                                       uint32_t addr) {
    asm volatile("ldmatrix.sync.aligned.m8n8.x4.shared.b16 {%0,%1,%2,%3}, [%4];"
                 : "=r"(r0), "=r"(r1), "=r"(r2), "=r"(r3) : "r"(addr));
}
__device__ __forceinline__ void mma_bf16(float* d, const uint32_t* a, uint32_t b0, uint32_t b1) {
    asm volatile(
        "mma.sync.aligned.m16n8k16.row.col.f32.bf16.bf16.f32 "
        "{%0,%1,%2,%3}, {%4,%5,%6,%7}, {%8,%9}, {%0,%1,%2,%3};"
        : "+f"(d[0]), "+f"(d[1]), "+f"(d[2]), "+f"(d[3])
        : "r"(a[0]), "r"(a[1]), "r"(a[2]), "r"(a[3]), "r"(b0), "r"(b1));
}

// ---------------- HMMA GEMM: C[M,N] = A[M,K] @ BT[N,K]^T + bias ----------------
// A,BT as bf16 (hi,lo) pairs; 3-term split product (AhBh + AhBl + AlBh), fp32 acc.
// BM=BN=128, BK=32, 256 threads, warp grid 2(M)x4(N), warp tile 64x32.
// EPI=0: fp32 out. EPI=1: exact GELU then bf16 hi/lo out.
#define ROWB   80                       // padded row pitch bytes (40 bf16)
#define TILEB2 (128*ROWB)               // 10240 B per tile
#define STAGEB (4*TILEB2)               // Ah|Al|Bh|Bl  = 40960 B
#define NSTG   3
#define GSMEM  (NSTG*STAGEB)            // 122880 B

__device__ __forceinline__ void load_stage(
    char* smem, int stage,
    const __nv_bfloat16* __restrict__ Ah, const __nv_bfloat16* __restrict__ Al,
    const __nv_bfloat16* __restrict__ Bh, const __nv_bfloat16* __restrict__ Bl,
    int bm, int bn, int M, int K, int k0, int tid, uint32_t sb)
{
#pragma unroll
    for (int i = 0; i < 8; i++) {
        const int c    = i * 256 + tid;
        const int tile = c >> 9;           // 0..3
        const int r    = (c >> 2) & 127;
        const int kc   = c & 3;
        const __nv_bfloat16* src = (tile == 0) ? Ah : (tile == 1) ? Al : (tile == 2) ? Bh : Bl;
        const int row0 = (tile < 2) ? bm : bn;
        int grow = row0 + r;
        int ok = 16;
        if (tile < 2 && grow >= M) { grow = 0; ok = 0; }
        const uint32_t dst = sb + stage * STAGEB + tile * TILEB2 + r * ROWB + kc * 16;
        cpa16(dst, src + (size_t)grow * K + k0 + kc * 8, ok);
    }
}

template<int EPI>
__global__ __launch_bounds__(256, 1)
void mma_gemm(const __nv_bfloat16* __restrict__ Ah, const __nv_bfloat16* __restrict__ Al,
              const __nv_bfloat16* __restrict__ Bh, const __nv_bfloat16* __restrict__ Bl,
              const float* __restrict__ bias,
              float* __restrict__ C,
              __nv_bfloat16* __restrict__ Ch, __nv_bfloat16* __restrict__ Cl,
              int M, int K, int N)
{
    extern __shared__ char smem[];
    const uint32_t sb = smem_u32(smem);
    const int tid = threadIdx.x, wid = tid >> 5, lane = tid & 31;
    const int bm = blockIdx.y * 128, bn = blockIdx.x * 128;
    const int wm = wid & 1, wn = wid >> 1;
    const int KT = K >> 5;

    float acc[4][4][4];
#pragma unroll
    for (int a = 0; a < 4; a++)
#pragma unroll
        for (int b = 0; b < 4; b++)
#pragma unroll
            for (int r = 0; r < 4; r++) acc[a][b][r] = 0.f;

    // prologue: 2 stages in flight
    load_stage(smem, 0, Ah, Al, Bh, Bl, bm, bn, M, K, 0, tid, sb);
    cpa_commit();
    load_stage(smem, 1, Ah, Al, Bh, Bl, bm, bn, M, K, 32, tid, sb);
    cpa_commit();

    const int lr = lane & 15, lc = lane >> 4;

    for (int kt = 0; kt < KT; kt++) {
        if (kt + 2 < KT)
            load_stage(smem, (kt + 2) % NSTG, Ah, Al, Bh, Bl, bm, bn, M, K, (kt + 2) * 32, tid, sb);
        cpa_commit();
        cpa_wait<2>();
        __syncthreads();

        const uint32_t st = sb + (kt % NSTG) * STAGEB;
#pragma unroll
        for (int kk = 0; kk < 2; kk++) {
            const uint32_t colo = kk * 32 + lc * 16;
            uint32_t ah[4][4], al[4][4], bh[2][4], bl[2][4];
#pragma unroll
            for (int mi = 0; mi < 4; mi++) {
                const uint32_t ra = (wm * 64 + mi * 16 + lr) * ROWB + colo;
                ldm_x4(ah[mi][0], ah[mi][1], ah[mi][2], ah[mi][3], st + 0 * TILEB2 + ra);
                ldm_x4(al[mi][0], al[mi][1], al[mi][2], al[mi][3], st + 1 * TILEB2 + ra);
            }
#pragma unroll
            for (int ni = 0; ni < 2; ni++) {
                const uint32_t rb = (wn * 32 + ni * 16 + lr) * ROWB + colo;
                ldm_x4(bh[ni][0], bh[ni][1], bh[ni][2], bh[ni][3], st + 2 * TILEB2 + rb);
                ldm_x4(bl[ni][0], bl[ni][1], bl[ni][2], bl[ni][3], st + 3 * TILEB2 + rb);
            }
#pragma unroll
            for (int mi = 0; mi < 4; mi++)
#pragma unroll
                for (int n = 0; n < 4; n++) {
                    const int ni = n >> 1, s = n & 1;
                    mma_bf16(acc[mi][n], ah[mi], bh[ni][s], bh[ni][s + 2]);
                    mma_bf16(acc[mi][n], ah[mi], bl[ni][s], bl[ni][s + 2]);
                    mma_bf16(acc[mi][n], al[mi], bh[ni][s], bh[ni][s + 2]);
                }
        }
        __syncthreads();
    }

    // epilogue
    const int g = lane >> 2, t2 = (lane & 3) * 2;
#pragma unroll
    for (int mi = 0; mi < 4; mi++) {
        const int r0 = bm + wm * 64 + mi * 16 + g;
#pragma unroll
        for (int n = 0; n < 4; n++) {
            const int col = bn + wn * 32 + n * 8 + t2;
            const float b0 = bias[col], b1 = bias[col + 1];
#pragma unroll
            for (int h = 0; h < 2; h++) {
                const int row = r0 + h * 8;
                if (row >= M) continue;
                float v0 = acc[mi][n][2 * h + 0] + b0;
                float v1 = acc[mi][n][2 * h + 1] + b1;
                if (EPI == 0) {
                    float2 o = make_float2(v0, v1);
                    *(float2*)(C + (size_t)row * N + col) = o;
                } else {
                    v0 = 0.5f * v0 * (1.f + erff(v0 * 0.70710678118654752f));
                    v1 = 0.5f * v1 * (1.f + erff(v1 * 0.70710678118654752f));
                    __nv_bfloat16 h0 = __float2bfloat16(v0), h1 = __float2bfloat16(v1);
                    __nv_bfloat16 l0 = __float2bfloat16(v0 - __bfloat162float(h0));
                    __nv_bfloat16 l1 = __float2bfloat16(v1 - __bfloat162float(h1));
                    const size_t o = (size_t)row * N + col;
                    *(uint32_t*)(Ch + o) = ((uint32_t)__bfloat16_as_ushort(h1) << 16) | __bfloat16_as_ushort(h0);
                    *(uint32_t*)(Cl + o) = ((uint32_t)__bfloat16_as_ushort(l1) << 16) | __bfloat16_as_ushort(l0);
                }
            }
        }
    }
}

// ---------------- prep kernels ----------------
__global__ void act_split(const float4* __restrict__ in, int n4,
                          __nv_bfloat16* __restrict__ h, __nv_bfloat16* __restrict__ l)
{
    const int i = blockIdx.x * blockDim.x + threadIdx.x;
    if (i >= n4) return;
    const float4 v = in[i];
    __nv_bfloat16 h0 = __float2bfloat16(v.x), h1 = __float2bfloat16(v.y);
    __nv_bfloat16 h2 = __float2bfloat16(v.z), h3 = __float2bfloat16(v.w);
    __nv_bfloat16 l0 = __float2bfloat16(v.x - __bfloat162float(h0));
    __nv_bfloat16 l1 = __float2bfloat16(v.y - __bfloat162float(h1));
    __nv_bfloat16 l2 = __float2bfloat16(v.z - __bfloat162float(h2));
    __nv_bfloat16 l3 = __float2bfloat16(v.w - __bfloat162float(h3));
    uint2 uh, ul;
    uh.x = ((uint32_t)__bfloat16_as_ushort(h1) << 16) | __bfloat16_as_ushort(h0);
    uh.y = ((uint32_t)__bfloat16_as_ushort(h3) << 16) | __bfloat16_as_ushort(h2);
    ul.x = ((uint32_t)__bfloat16_as_ushort(l1) << 16) | __bfloat16_as_ushort(l0);
    ul.y = ((uint32_t)__bfloat16_as_ushort(l3) << 16) | __bfloat16_as_ushort(l2);
    *(uint2*)(h + (size_t)i * 4) = uh;
    *(uint2*)(l + (size_t)i * 4) = ul;
}

__global__ void wt_split(const float* __restrict__ W, int K, int N,
                         __nv_bfloat16* __restrict__ Th, __nv_bfloat16* __restrict__ Tl)
{
    const int i = blockIdx.x * blockDim.x + threadIdx.x;
    if (i >= N * K) return;
    const int n = i / K, k = i % K;
    const float v = W[(size_t)k * N + n];
    const __nv_bfloat16 h = __float2bfloat16(v);
    Th[i] = h;
    Tl[i] = __float2bfloat16(v - __bfloat162float(h));
}

__global__ void build_bq(const float* __restrict__ boff, const float* __restrict__ battn,
                         const float* __restrict__ bref, float* __restrict__ bq,
                         __nv_bfloat16* __restrict__ Th, __nv_bfloat16* __restrict__ Tl)
{
    const int i = blockIdx.x * blockDim.x + threadIdx.x;
    if (i < NQC)
        bq[i] = (i < 192) ? boff[i] : (i < 288) ? battn[i - 192] : (i < 290) ? bref[i - 288] : 0.f;
    const int padN = (NQC - 290) * Dm;
    if (i < padN) {
        Th[290 * Dm + i] = __float2bfloat16(0.f);
        Tl[290 * Dm + i] = __float2bfloat16(0.f);
    }
}

// ---------------- fused softmax + sigmoid + bilinear sampling ----------------
__global__ __launch_bounds__(256)
void sample_kernel(__nv_bfloat16* __restrict__ oh, __nv_bfloat16* __restrict__ ol)
{
    const int t    = blockIdx.x;
    const int b    = t / NTOK;
    const int tid  = threadIdx.x;
    const int h    = tid >> 5;
    const int lane = tid & 31;

    __shared__ float s_aw[96], s_x[96], s_y[96];

    const float refx = 1.f / (1.f + __expf(-g_qcat[(size_t)t * NQC + 288]));
    const float refy = 1.f / (1.f + __expf(-g_qcat[(size_t)t * NQC + 289]));

    if (tid < 96) {
        const int lp = tid % 12;
        const int l  = lp >> 2;
        const float ox = g_qcat[(size_t)t * NQC + tid * 2 + 0];
        const float oy = g_qcat[(size_t)t * NQC + tid * 2 + 1];
        s_x[tid]  = fmaf(refx, (float)c_lvlW[l], ox) - 0.5f;
        s_y[tid]  = fmaf(refy, (float)c_lvlH[l], oy) - 0.5f;
        s_aw[tid] = g_qcat[(size_t)t * NQC + 192 + tid];
    }
    __syncthreads();

    if (tid < 8) {
        float m = -1e30f;
#pragma unroll
        for (int j = 0; j < 12; j++) m = fmaxf(m, s_aw[tid * 12 + j]);
        float s = 0.f;
#pragma unroll
        for (int j = 0; j < 12; j++) { const float e = __expf(s_aw[tid * 12 + j] - m); s_aw[tid * 12 + j] = e; s += e; }
        const float inv = 1.f / s;
#pragma unroll
        for (int j = 0; j < 12; j++) s_aw[tid * 12 + j] *= inv;
    }
    __syncthreads();

    float acc = 0.f;
#pragma unroll
    for (int l = 0; l < 3; l++) {
        const int Hl = c_lvlH[l], Wl = c_lvlW[l];
        const float* vl = g_val + c_lvlOff[l] + (size_t)b * c_lvlN[l] * Dm + (h * DHd + lane);
#pragma unroll
        for (int p = 0; p < 4; p++) {
            const int idx = h * 12 + l * 4 + p;
            const float x = s_x[idx], y = s_y[idx], w = s_aw[idx];
            const float x0f = floorf(x), y0f = floorf(y);
            const int x0 = (int)x0f, y0 = (int)y0f;
            const float lx = x - x0f, ly = y - y0f;
            const float w00 = (1.f - lx) * (1.f - ly);
            const float w01 = lx * (1.f - ly);
            const float w10 = (1.f - lx) * ly;
            const float w11 = lx * ly;
            float v = 0.f;
            const bool xin0 = (x0 >= 0) & (x0 < Wl);
            const bool xin1 = (x0 + 1 >= 0) & (x0 + 1 < Wl);
            const bool yin0 = (y0 >= 0) & (y0 < Hl);
            const bool yin1 = (y0 + 1 >= 0) & (y0 + 1 < Hl);
            if (xin0 & yin0) v = fmaf(w00, vl[(size_t)(y0 * Wl + x0) * Dm], v);
            if (xin1 & yin0) v = fmaf(w01, vl[(size_t)(y0 * Wl + x0 + 1) * Dm], v);
            if (xin0 & yin1) v = fmaf(w10, vl[(size_t)((y0 + 1) * Wl + x0) * Dm], v);
            if (xin1 & yin1) v = fmaf(w11, vl[(size_t)((y0 + 1) * Wl + x0 + 1) * Dm], v);
            acc = fmaf(w, v, acc);
        }
    }
    const __nv_bfloat16 hv = __float2bfloat16(acc);
    oh[(size_t)t * Dm + h * DHd + lane] = hv;
    ol[(size_t)t * Dm + h * DHd + lane] = __float2bfloat16(acc - __bfloat162float(hv));
}

// ---------------- residual + LayerNorm ----------------
template<int EMIT>
__global__ __launch_bounds__(256)
void ln_residual(const float* __restrict__ x, const float* __restrict__ y,
                 const float* __restrict__ g, const float* __restrict__ be,
                 float* __restrict__ out,
                 __nv_bfloat16* __restrict__ oh, __nv_bfloat16* __restrict__ ol)
{
    const int t = blockIdx.x, tid = threadIdx.x;
    const float v = x[(size_t)t * Dm + tid] + y[(size_t)t * Dm + tid];

    __shared__ float sh[18];
    float s = v, sq = v * v;
#pragma unroll
    for (int o = 16; o; o >>= 1) {
        s  += __shfl_xor_sync(0xffffffffu, s,  o);
        sq += __shfl_xor_sync(0xffffffffu, sq, o);
    }
    const int w = tid >> 5, lane = tid & 31;
    if (lane == 0) { sh[w] = s; sh[w + 8] = sq; }
    __syncthreads();
    if (tid == 0) {
        float ts = 0.f, tq = 0.f;
#pragma unroll
        for (int i = 0; i < 8; i++) { ts += sh[i]; tq += sh[i + 8]; }
        sh[16] = ts * (1.f / Dm);
        sh[17] = tq * (1.f / Dm);
    }
    __syncthreads();
    const float mean = sh[16];
    const float var  = fmaxf(sh[17] - mean * mean, 0.f);
    const float inv  = rsqrtf(var + 1e-5f);
    const float o = (v - mean) * inv * g[tid] + be[tid];
    out[(size_t)t * Dm + tid] = o;
    if (EMIT) {
        const __nv_bfloat16 hv = __float2bfloat16(o);
        oh[(size_t)t * Dm + tid] = hv;
        ol[(size_t)t * Dm + tid] = __float2bfloat16(o - __bfloat162float(hv));
    }
}

// ---------------- host orchestration ----------------
extern "C" void kernel_launch(void* const* d_in, const int* in_sizes, int n_in,
                              void* d_out, int out_size)
{
    const float* query = (const float*)d_in[0];
    const float* p3    = (const float*)d_in[1];
    const float* p4    = (const float*)d_in[2];
    const float* p5    = (const float*)d_in[3];
    const float* Wv    = (const float*)d_in[4];
    const float* bv    = (const float*)d_in[5];
    const float* Woff  = (const float*)d_in[6];
    const float* boff  = (const float*)d_in[7];
    const float* Wattn = (const float*)d_in[8];
    const float* battn = (const float*)d_in[9];
    const float* Wref  = (const float*)d_in[10];
    const float* bref  = (const float*)d_in[11];
    const float* Wo    = (const float*)d_in[12];
    const float* bo    = (const float*)d_in[13];
    const float* W1    = (const float*)d_in[14];
    const float* b1    = (const float*)d_in[15];
    const float* W2    = (const float*)d_in[16];
    const float* b2    = (const float*)d_in[17];
    const float* g1    = (const float*)d_in[18];
    const float* be1   = (const float*)d_in[19];
    const float* g2    = (const float*)d_in[20];
    const float* be2   = (const float*)d_in[21];
    float* out = (float*)d_out;

    cudaFuncSetAttribute(mma_gemm<0>, cudaFuncAttributeMaxDynamicSharedMemorySize, GSMEM);
    cudaFuncSetAttribute(mma_gemm<1>, cudaFuncAttributeMaxDynamicSharedMemorySize, GSMEM);

#define SYM(T, p, s) T* p; cudaGetSymbolAddress((void**)&p, s)
    SYM(__nv_bfloat16, valin_h, g_valin_h); SYM(__nv_bfloat16, valin_l, g_valin_l);
    SYM(float, val, g_val);
    SYM(__nv_bfloat16, qh, g_qh); SYM(__nv_bfloat16, ql, g_ql);
    SYM(float, qcat, g_qcat);
    SYM(__nv_bfloat16, sah, g_sah); SYM(__nv_bfloat16, sal, g_sal);
    SYM(float, bufB, g_bufB); SYM(float, qf, g_q);
    SYM(__nv_bfloat16, qnh, g_qnh); SYM(__nv_bfloat16, qnl, g_qnl);
    SYM(__nv_bfloat16, h1h, g_h1h); SYM(__nv_bfloat16, h1l, g_h1l);
    SYM(__nv_bfloat16, WvTh, g_WvT_h); SYM(__nv_bfloat16, WvTl, g_WvT_l);
    SYM(__nv_bfloat16, WqTh, g_WqT_h); SYM(__nv_bfloat16, WqTl, g_WqT_l);
    SYM(__nv_bfloat16, WoTh, g_WoT_h); SYM(__nv_bfloat16, WoTl, g_WoT_l);
    SYM(__nv_bfloat16, W1Th, g_W1T_h); SYM(__nv_bfloat16, W1Tl, g_W1T_l);
    SYM(__nv_bfloat16, W2Th, g_W2T_h); SYM(__nv_bfloat16, W2Tl, g_W2T_l);
    SYM(float, bq, g_bq);
#undef SYM

    // ---- weight prep ----
    wt_split<<<(Dm * Dm + 255) / 256, 256>>>(Wv, Dm, Dm, WvTh, WvTl);
    wt_split<<<(192 * Dm + 255) / 256, 256>>>(Woff,  Dm, 192, WqTh,            WqTl);
    wt_split<<<(96  * Dm + 255) / 256, 256>>>(Wattn, Dm, 96,  WqTh + 192 * Dm, WqTl + 192 * Dm);
    wt_split<<<(2   * Dm + 255) / 256, 256>>>(Wref,  Dm, 2,   WqTh + 288 * Dm, WqTl + 288 * Dm);
    build_bq<<<((NQC - 290) * Dm + 255) / 256, 256>>>(boff, battn, bref, bq, WqTh, WqTl);
    wt_split<<<(Dm * Dm + 255) / 256, 256>>>(Wo, Dm, Dm, WoTh, WoTl);
    wt_split<<<(FFd * Dm + 255) / 256, 256>>>(W1, Dm, FFd, W1Th, W1Tl);
    wt_split<<<(Dm * FFd + 255) / 256, 256>>>(W2, FFd, Dm, W2Th, W2Tl);

    // ---- activation splits ----
    const int nq4 = MTOT * Dm / 4;
    act_split<<<(nq4 + 255) / 256, 256>>>((const float4*)query, nq4, qh, ql);
    const int n3 = Bsz * 10000 * Dm / 4, n4v = Bsz * 2500 * Dm / 4, n5 = Bsz * 625 * Dm / 4;
    act_split<<<(n3  + 255) / 256, 256>>>((const float4*)p3, n3,  valin_h, valin_l);
    act_split<<<(n4v + 255) / 256, 256>>>((const float4*)p4, n4v, valin_h + (size_t)n3 * 4, valin_l + (size_t)n3 * 4);
    act_split<<<(n5  + 255) / 256, 256>>>((const float4*)p5, n5,  valin_h + (size_t)(n3 + n4v) * 4, valin_l + (size_t)(n3 + n4v) * 4);

    const int TM = (MTOT + 127) / 128;   // 411

    // ---- value projection ----
    mma_gemm<0><<<dim3(2, TM), 256, GSMEM>>>(valin_h, valin_l, WvTh, WvTl, bv,
                                             val, nullptr, nullptr, MTOT, Dm, Dm);
    // ---- fused q projections (off|attn|ref) ----
    mma_gemm<0><<<dim3(3, TM), 256, GSMEM>>>(qh, ql, WqTh, WqTl, bq,
                                             qcat, nullptr, nullptr, MTOT, Dm, NQC);
    // ---- sampling ----
    sample_kernel<<<MTOT, 256>>>(sah, sal);
    // ---- output projection + LN1 ----
    mma_gemm<0><<<dim3(2, TM), 256, GSMEM>>>(sah, sal, WoTh, WoTl, bo,
                                             bufB, nullptr, nullptr, MTOT, Dm, Dm);
    ln_residual<1><<<MTOT, 256>>>(query, bufB, g1, be1, qf, qnh, qnl);
    // ---- FFN ----
    mma_gemm<1><<<dim3(8, TM), 256, GSMEM>>>(qnh, qnl, W1Th, W1Tl, b1,
                                             nullptr, h1h, h1l, MTOT, Dm, FFd);
    mma_gemm<0><<<dim3(2, TM), 256, GSMEM>>>(h1h, h1l, W2Th, W2Tl, b2,
                                             bufB, nullptr, nullptr, MTOT, FFd, Dm);
    ln_residual<0><<<MTOT, 256>>>(qf, bufB, g2, be2, out, nullptr, nullptr);
}

// round 4
// speedup vs baseline: 3.0436x; 1.4092x over previous
#include <cuda_runtime.h>
#include <cuda_fp16.h>
#include <math.h>
#include <cstdint>

// ---------------- problem constants ----------------
#define Bsz   4
#define NTOK  13125
#define MTOT  (Bsz*NTOK)      // 52500
#define Dm    256
#define NHd   8
#define DHd   32
#define FFd   1024
#define NQC   384             // fused q-proj width: 192 off | 96 attn | 2 ref | 94 pad

__device__ __constant__ int    c_lvlH[3] = {100, 50, 25};
__device__ __constant__ int    c_lvlW[3] = {100, 50, 25};
__device__ __constant__ int    c_lvlN[3] = {10000, 2500, 625};
__device__ __constant__ size_t c_lvlOff[3] = {0, (size_t)Bsz*10000*Dm,
                                              (size_t)Bsz*10000*Dm + (size_t)Bsz*2500*Dm};

// ---------------- scratch (__device__ globals; no allocations) ----------------
__device__ __align__(16) __half g_valin_h[(size_t)MTOT*Dm], g_valin_l[(size_t)MTOT*Dm];
__device__ __align__(16) float  g_val   [(size_t)MTOT*Dm];
__device__ __align__(16) __half g_qh    [(size_t)MTOT*Dm], g_ql[(size_t)MTOT*Dm];
__device__ __align__(16) float  g_qcat  [(size_t)MTOT*NQC];
__device__ __align__(16) __half g_sah   [(size_t)MTOT*Dm], g_sal[(size_t)MTOT*Dm];
__device__ __align__(16) float  g_bufB  [(size_t)MTOT*Dm];
__device__ __align__(16) float  g_q     [(size_t)MTOT*Dm];
__device__ __align__(16) __half g_qnh   [(size_t)MTOT*Dm], g_qnl[(size_t)MTOT*Dm];
__device__ __align__(16) __half g_h1h   [(size_t)MTOT*FFd], g_h1l[(size_t)MTOT*FFd];

__device__ __align__(16) __half g_WvT [Dm*Dm];
__device__ __align__(16) __half g_WqT [NQC*Dm];
__device__ __align__(16) __half g_WoT [Dm*Dm];
__device__ __align__(16) __half g_W1T [FFd*Dm];
__device__ __align__(16) __half g_W2T [Dm*FFd];
__device__ float  g_bq[NQC];

// ---------------- baseline-PTX primitives ----------------
__device__ __forceinline__ uint32_t smem_u32(const void* p) {
    uint32_t a;
    asm("{ .reg .u64 t; cvta.to.shared.u64 t, %1; cvt.u32.u64 %0, t; }" : "=r"(a) : "l"(p));
    return a;
}
__device__ __forceinline__ void cpa16(uint32_t dst, const void* src, int srcBytes) {
    asm volatile("cp.async.cg.shared.global [%0], [%1], 16, %2;"
                 :: "r"(dst), "l"(src), "r"(srcBytes) : "memory");
}
__device__ __forceinline__ void cpa_commit() {
    asm volatile("cp.async.commit_group;" ::: "memory");
}
template<int N> __device__ __forceinline__ void cpa_wait() {
    asm volatile("cp.async.wait_group %0;" :: "n"(N) : "memory");
}
__device__ __forceinline__ void ldm_x4(uint32_t& r0, uint32_t& r1, uint32_t& r2, uint32_t& r3,
                                       uint32_t addr) {
    asm volatile("ldmatrix.sync.aligned.m8n8.x4.shared.b16 {%0,%1,%2,%3}, [%4];"
                 : "=r"(r0), "=r"(r1), "=r"(r2), "=r"(r3) : "r"(addr));
}
__device__ __forceinline__ void mma_f16(float* d, const uint32_t* a, uint32_t b0, uint32_t b1) {
    asm volatile(
        "mma.sync.aligned.m16n8k16.row.col.f32.f16.f16.f32 "
        "{%0,%1,%2,%3}, {%4,%5,%6,%7}, {%8,%9}, {%0,%1,%2,%3};"
        : "+f"(d[0]), "+f"(d[1]), "+f"(d[2]), "+f"(d[3])
        : "r"(a[0]), "r"(a[1]), "r"(a[2]), "r"(a[3]), "r"(b0), "r"(b1));
}
__device__ __forceinline__ uint32_t pack_h2(float a, float b) {
    __half h0 = __float2half_rn(a), h1 = __float2half_rn(b);
    return ((uint32_t)__half_as_ushort(h1) << 16) | __half_as_ushort(h0);
}

// ---------------- HMMA GEMM: C[M,N] = (Ah+Al)[M,K] @ BhT[N,K]^T + bias ------
// 2-term fp16 split (A split hi/lo, B single fp16). fp32 accumulate.
// BM=BN=128, BK=32, 256 threads, warp grid 2(M)x4(N), 4-stage cp.async pipeline.
#define ROWB   80                       // padded row pitch bytes (40 halves)
#define TILEB2 (128*ROWB)               // 10240 B per tile
#define STAGEB (3*TILEB2)               // Ah|Al|Bh = 30720 B
#define NSTG   4
#define GSMEM  (NSTG*STAGEB)            // 122880 B

__device__ __forceinline__ void load_stage(
    int stage,
    const __half* __restrict__ Ah, const __half* __restrict__ Al,
    const __half* __restrict__ Bh,
    int bm, int bn, int M, int K, int k0, int tid, uint32_t sb)
{
#pragma unroll
    for (int i = 0; i < 6; i++) {
        const int c    = i * 256 + tid;        // 0..1535
        const int tile = c >> 9;               // 0..2
        const int r    = (c >> 2) & 127;
        const int kc   = c & 3;
        const __half* src = (tile == 0) ? Ah : (tile == 1) ? Al : Bh;
        const int row0 = (tile < 2) ? bm : bn;
        int grow = row0 + r;
        int ok = 16;
        if (tile < 2 && grow >= M) { grow = 0; ok = 0; }
        const uint32_t dst = sb + stage * STAGEB + tile * TILEB2 + r * ROWB + kc * 16;
        cpa16(dst, src + (size_t)grow * K + k0 + kc * 8, ok);
    }
}

template<int EPI>
__global__ __launch_bounds__(256, 1)
void mma_gemm(const __half* __restrict__ Ah, const __half* __restrict__ Al,
              const __half* __restrict__ Bh,
              const float* __restrict__ bias,
              float* __restrict__ C,
              __half* __restrict__ Ch, __half* __restrict__ Cl,
              int M, int K, int N)
{
    extern __shared__ char smem[];
    const uint32_t sb = smem_u32(smem);
    const int tid = threadIdx.x, wid = tid >> 5, lane = tid & 31;
    const int bm = blockIdx.y * 128, bn = blockIdx.x * 128;
    const int wm = wid & 1, wn = wid >> 1;
    const int KT = K >> 5;

    float acc[4][4][4];
#pragma unroll
    for (int a = 0; a < 4; a++)
#pragma unroll
        for (int b = 0; b < 4; b++)
#pragma unroll
            for (int r = 0; r < 4; r++) acc[a][b][r] = 0.f;

    // prologue: 3 stages in flight
    load_stage(0, Ah, Al, Bh, bm, bn, M, K, 0,  tid, sb); cpa_commit();
    load_stage(1, Ah, Al, Bh, bm, bn, M, K, 32, tid, sb); cpa_commit();
    load_stage(2, Ah, Al, Bh, bm, bn, M, K, 64, tid, sb); cpa_commit();

    const int lr = lane & 15, lc = lane >> 4;

    for (int kt = 0; kt < KT; kt++) {
        if (kt + 3 < KT)
            load_stage((kt + 3) % NSTG, Ah, Al, Bh, bm, bn, M, K, (kt + 3) * 32, tid, sb);
        cpa_commit();
        cpa_wait<3>();
        __syncthreads();

        const uint32_t st = sb + (kt % NSTG) * STAGEB;
#pragma unroll
        for (int kk = 0; kk < 2; kk++) {
            const uint32_t colo = kk * 32 + lc * 16;
            uint32_t ah[4][4], al[4][4], bh[2][4];
#pragma unroll
            for (int mi = 0; mi < 4; mi++) {
                const uint32_t ra = (wm * 64 + mi * 16 + lr) * ROWB + colo;
                ldm_x4(ah[mi][0], ah[mi][1], ah[mi][2], ah[mi][3], st + 0 * TILEB2 + ra);
                ldm_x4(al[mi][0], al[mi][1], al[mi][2], al[mi][3], st + 1 * TILEB2 + ra);
            }
#pragma unroll
            for (int ni = 0; ni < 2; ni++) {
                const uint32_t rb = (wn * 32 + ni * 16 + lr) * ROWB + colo;
                ldm_x4(bh[ni][0], bh[ni][1], bh[ni][2], bh[ni][3], st + 2 * TILEB2 + rb);
            }
#pragma unroll
            for (int mi = 0; mi < 4; mi++)
#pragma unroll
                for (int n = 0; n < 4; n++) {
                    const int ni = n >> 1, s = n & 1;
                    mma_f16(acc[mi][n], ah[mi], bh[ni][s], bh[ni][s + 2]);
                    mma_f16(acc[mi][n], al[mi], bh[ni][s], bh[ni][s + 2]);
                }
        }
        __syncthreads();
    }

    // epilogue
    const int g = lane >> 2, t2 = (lane & 3) * 2;
#pragma unroll
    for (int mi = 0; mi < 4; mi++) {
        const int r0 = bm + wm * 64 + mi * 16 + g;
#pragma unroll
        for (int n = 0; n < 4; n++) {
            const int col = bn + wn * 32 + n * 8 + t2;
            const float b0 = bias[col], b1 = bias[col + 1];
#pragma unroll
            for (int h = 0; h < 2; h++) {
                const int row = r0 + h * 8;
                if (row >= M) continue;
                float v0 = acc[mi][n][2 * h + 0] + b0;
                float v1 = acc[mi][n][2 * h + 1] + b1;
                if (EPI == 0) {
                    *(float2*)(C + (size_t)row * N + col) = make_float2(v0, v1);
                } else {
                    v0 = 0.5f * v0 * (1.f + erff(v0 * 0.70710678118654752f));
                    v1 = 0.5f * v1 * (1.f + erff(v1 * 0.70710678118654752f));
                    __half h0 = __float2half_rn(v0), h1 = __float2half_rn(v1);
                    float  r0f = v0 - __half2float(h0), r1f = v1 - __half2float(h1);
                    const size_t o = (size_t)row * N + col;
                    *(uint32_t*)(Ch + o) = ((uint32_t)__half_as_ushort(h1) << 16) | __half_as_ushort(h0);
                    *(uint32_t*)(Cl + o) = pack_h2(r0f, r1f);
                }
            }
        }
    }
}

// ---------------- prep kernels ----------------
__global__ void act_split(const float4* __restrict__ in, int n4,
                          __half* __restrict__ h, __half* __restrict__ l)
{
    const int i = blockIdx.x * blockDim.x + threadIdx.x;
    if (i >= n4) return;
    const float4 v = in[i];
    __half h0 = __float2half_rn(v.x), h1 = __float2half_rn(v.y);
    __half h2 = __float2half_rn(v.z), h3 = __float2half_rn(v.w);
    uint2 uh, ul;
    uh.x = ((uint32_t)__half_as_ushort(h1) << 16) | __half_as_ushort(h0);
    uh.y = ((uint32_t)__half_as_ushort(h3) << 16) | __half_as_ushort(h2);
    ul.x = pack_h2(v.x - __half2float(h0), v.y - __half2float(h1));
    ul.y = pack_h2(v.z - __half2float(h2), v.w - __half2float(h3));
    *(uint2*)(h + (size_t)i * 4) = uh;
    *(uint2*)(l + (size_t)i * 4) = ul;
}

// transpose W[K,N] -> T[N,K] fp16
__global__ void wt_half(const float* __restrict__ W, int K, int N,
                        __half* __restrict__ T)
{
    const int i = blockIdx.x * blockDim.x + threadIdx.x;
    if (i >= N * K) return;
    const int n = i / K, k = i % K;
    T[i] = __float2half_rn(W[(size_t)k * N + n]);
}

__global__ void build_bq(const float* __restrict__ boff, const float* __restrict__ battn,
                         const float* __restrict__ bref, float* __restrict__ bq,
                         __half* __restrict__ T)
{
    const int i = blockIdx.x * blockDim.x + threadIdx.x;
    if (i < NQC)
        bq[i] = (i < 192) ? boff[i] : (i < 288) ? battn[i - 192] : (i < 290) ? bref[i - 288] : 0.f;
    const int padN = (NQC - 290) * Dm;
    if (i < padN) T[290 * Dm + i] = __float2half_rn(0.f);
}

// ---------------- fused softmax + sigmoid + bilinear sampling ----------------
// 64 threads per token (4 tokens per 256-thread block); thread = (head, 4-channel group)
__global__ __launch_bounds__(256)
void sample_kernel(__half* __restrict__ oh, __half* __restrict__ ol)
{
    const int tid  = threadIdx.x;
    const int sub  = tid >> 6;                 // token within block
    const int t    = blockIdx.x * 4 + sub;
    const int b    = t / NTOK;
    const int tid2 = tid & 63;
    const int h    = tid2 >> 3;                // head 0..7
    const int cg   = tid2 & 7;                 // channel group (4 ch)

    __shared__ float s_aw[4][96], s_x[4][96], s_y[4][96];

    const float refx = 1.f / (1.f + __expf(-g_qcat[(size_t)t * NQC + 288]));
    const float refy = 1.f / (1.f + __expf(-g_qcat[(size_t)t * NQC + 289]));

    for (int i = tid2; i < 96; i += 64) {
        const int lp = i % 12;
        const int l  = lp >> 2;
        const float ox = g_qcat[(size_t)t * NQC + i * 2 + 0];
        const float oy = g_qcat[(size_t)t * NQC + i * 2 + 1];
        s_x[sub][i]  = fmaf(refx, (float)c_lvlW[l], ox) - 0.5f;
        s_y[sub][i]  = fmaf(refy, (float)c_lvlH[l], oy) - 0.5f;
        s_aw[sub][i] = g_qcat[(size_t)t * NQC + 192 + i];
    }
    __syncthreads();

    if (tid2 < 8) {    // per-head softmax over 12 (l,p)
        float m = -1e30f;
#pragma unroll
        for (int j = 0; j < 12; j++) m = fmaxf(m, s_aw[sub][tid2 * 12 + j]);
        float s = 0.f;
#pragma unroll
        for (int j = 0; j < 12; j++) {
            const float e = __expf(s_aw[sub][tid2 * 12 + j] - m);
            s_aw[sub][tid2 * 12 + j] = e; s += e;
        }
        const float inv = 1.f / s;
#pragma unroll
        for (int j = 0; j < 12; j++) s_aw[sub][tid2 * 12 + j] *= inv;
    }
    __syncthreads();

    float4 acc = make_float4(0.f, 0.f, 0.f, 0.f);
#pragma unroll
    for (int l = 0; l < 3; l++) {
        const int Hl = c_lvlH[l], Wl = c_lvlW[l];
        const float* vl = g_val + c_lvlOff[l] + (size_t)b * c_lvlN[l] * Dm + (h * DHd + cg * 4);
#pragma unroll
        for (int p = 0; p < 4; p++) {
            const int idx = h * 12 + l * 4 + p;
            const float x = s_x[sub][idx], y = s_y[sub][idx], w = s_aw[sub][idx];
            const float x0f = floorf(x), y0f = floorf(y);
            const int x0 = (int)x0f, y0 = (int)y0f;
            const float lx = x - x0f, ly = y - y0f;
            const float w00 = w * (1.f - lx) * (1.f - ly);
            const float w01 = w * lx * (1.f - ly);
            const float w10 = w * (1.f - lx) * ly;
            const float w11 = w * lx * ly;
            const bool xin0 = (x0 >= 0) & (x0 < Wl);
            const bool xin1 = (x0 + 1 >= 0) & (x0 + 1 < Wl);
            const bool yin0 = (y0 >= 0) & (y0 < Hl);
            const bool yin1 = (y0 + 1 >= 0) & (y0 + 1 < Hl);
#define ACC4(cond, wgt, ro, co) \
            if (cond) { \
                const float4 v = *(const float4*)(vl + (size_t)((ro) * Wl + (co)) * Dm); \
                acc.x = fmaf(wgt, v.x, acc.x); acc.y = fmaf(wgt, v.y, acc.y); \
                acc.z = fmaf(wgt, v.z, acc.z); acc.w = fmaf(wgt, v.w, acc.w); \
            }
            ACC4(xin0 & yin0, w00, y0,     x0)
            ACC4(xin1 & yin0, w01, y0,     x0 + 1)
            ACC4(xin0 & yin1, w10, y0 + 1, x0)
            ACC4(xin1 & yin1, w11, y0 + 1, x0 + 1)
#undef ACC4
        }
    }
    const size_t o = (size_t)t * Dm + h * DHd + cg * 4;
    uint2 uh, ul;
    __half h0 = __float2half_rn(acc.x), h1 = __float2half_rn(acc.y);
    __half h2 = __float2half_rn(acc.z), h3 = __float2half_rn(acc.w);
    uh.x = ((uint32_t)__half_as_ushort(h1) << 16) | __half_as_ushort(h0);
    uh.y = ((uint32_t)__half_as_ushort(h3) << 16) | __half_as_ushort(h2);
    ul.x = pack_h2(acc.x - __half2float(h0), acc.y - __half2float(h1));
    ul.y = pack_h2(acc.z - __half2float(h2), acc.w - __half2float(h3));
    *(uint2*)(oh + o) = uh;
    *(uint2*)(ol + o) = ul;
}

// ---------------- residual + LayerNorm ----------------
template<int EMIT>
__global__ __launch_bounds__(256)
void ln_residual(const float* __restrict__ x, const float* __restrict__ y,
                 const float* __restrict__ g, const float* __restrict__ be,
                 float* __restrict__ out,
                 __half* __restrict__ oh, __half* __restrict__ ol)
{
    const int t = blockIdx.x, tid = threadIdx.x;
    const float v = x[(size_t)t * Dm + tid] + y[(size_t)t * Dm + tid];

    __shared__ float sh[18];
    float s = v, sq = v * v;
#pragma unroll
    for (int o = 16; o; o >>= 1) {
        s  += __shfl_xor_sync(0xffffffffu, s,  o);
        sq += __shfl_xor_sync(0xffffffffu, sq, o);
    }
    const int w = tid >> 5, lane = tid & 31;
    if (lane == 0) { sh[w] = s; sh[w + 8] = sq; }
    __syncthreads();
    if (tid == 0) {
        float ts = 0.f, tq = 0.f;
#pragma unroll
        for (int i = 0; i < 8; i++) { ts += sh[i]; tq += sh[i + 8]; }
        sh[16] = ts * (1.f / Dm);
        sh[17] = tq * (1.f / Dm);
    }
    __syncthreads();
    const float mean = sh[16];
    const float var  = fmaxf(sh[17] - mean * mean, 0.f);
    const float inv  = rsqrtf(var + 1e-5f);
    const float o = (v - mean) * inv * g[tid] + be[tid];
    out[(size_t)t * Dm + tid] = o;
    if (EMIT) {
        const __half hv = __float2half_rn(o);
        oh[(size_t)t * Dm + tid] = hv;
        ol[(size_t)t * Dm + tid] = __float2half_rn(o - __half2float(hv));
    }
}

// ---------------- host orchestration ----------------
extern "C" void kernel_launch(void* const* d_in, const int* in_sizes, int n_in,
                              void* d_out, int out_size)
{
    const float* query = (const float*)d_in[0];
    const float* p3    = (const float*)d_in[1];
    const float* p4    = (const float*)d_in[2];
    const float* p5    = (const float*)d_in[3];
    const float* Wv    = (const float*)d_in[4];
    const float* bv    = (const float*)d_in[5];
    const float* Woff  = (const float*)d_in[6];
    const float* boff  = (const float*)d_in[7];
    const float* Wattn = (const float*)d_in[8];
    const float* battn = (const float*)d_in[9];
    const float* Wref  = (const float*)d_in[10];
    const float* bref  = (const float*)d_in[11];
    const float* Wo    = (const float*)d_in[12];
    const float* bo    = (const float*)d_in[13];
    const float* W1    = (const float*)d_in[14];
    const float* b1    = (const float*)d_in[15];
    const float* W2    = (const float*)d_in[16];
    const float* b2    = (const float*)d_in[17];
    const float* g1    = (const float*)d_in[18];
    const float* be1   = (const float*)d_in[19];
    const float* g2    = (const float*)d_in[20];
    const float* be2   = (const float*)d_in[21];
    float* out = (float*)d_out;

    cudaFuncSetAttribute(mma_gemm<0>, cudaFuncAttributeMaxDynamicSharedMemorySize, GSMEM);
    cudaFuncSetAttribute(mma_gemm<1>, cudaFuncAttributeMaxDynamicSharedMemorySize, GSMEM);

#define SYM(T, p, s) T* p; cudaGetSymbolAddress((void**)&p, s)
    SYM(__half, valin_h, g_valin_h); SYM(__half, valin_l, g_valin_l);
    SYM(float, val, g_val);
    SYM(__half, qh, g_qh); SYM(__half, ql, g_ql);
    SYM(float, qcat, g_qcat);
    SYM(__half, sah, g_sah); SYM(__half, sal, g_sal);
    SYM(float, bufB, g_bufB); SYM(float, qf, g_q);
    SYM(__half, qnh, g_qnh); SYM(__half, qnl, g_qnl);
    SYM(__half, h1h, g_h1h); SYM(__half, h1l, g_h1l);
    SYM(__half, WvT, g_WvT); SYM(__half, WqT, g_WqT);
    SYM(__half, WoT, g_WoT); SYM(__half, W1T, g_W1T); SYM(__half, W2T, g_W2T);
    SYM(float, bq, g_bq);
#undef SYM

    // ---- weight prep (fp16 transposed) ----
    wt_half<<<(Dm * Dm + 255) / 256, 256>>>(Wv, Dm, Dm, WvT);
    wt_half<<<(192 * Dm + 255) / 256, 256>>>(Woff,  Dm, 192, WqT);
    wt_half<<<(96  * Dm + 255) / 256, 256>>>(Wattn, Dm, 96,  WqT + 192 * Dm);
    wt_half<<<(2   * Dm + 255) / 256, 256>>>(Wref,  Dm, 2,   WqT + 288 * Dm);
    build_bq<<<((NQC - 290) * Dm + 255) / 256, 256>>>(boff, battn, bref, bq, WqT);
    wt_half<<<(Dm * Dm + 255) / 256, 256>>>(Wo, Dm, Dm, WoT);
    wt_half<<<(FFd * Dm + 255) / 256, 256>>>(W1, Dm, FFd, W1T);
    wt_half<<<(Dm * FFd + 255) / 256, 256>>>(W2, FFd, Dm, W2T);

    // ---- activation splits (fp16 hi/lo) ----
    const int nq4 = MTOT * Dm / 4;
    act_split<<<(nq4 + 255) / 256, 256>>>((const float4*)query, nq4, qh, ql);
    const int n3 = Bsz * 10000 * Dm / 4, n4v = Bsz * 2500 * Dm / 4, n5 = Bsz * 625 * Dm / 4;
    act_split<<<(n3  + 255) / 256, 256>>>((const float4*)p3, n3,  valin_h, valin_l);
    act_split<<<(n4v + 255) / 256, 256>>>((const float4*)p4, n4v, valin_h + (size_t)n3 * 4, valin_l + (size_t)n3 * 4);
    act_split<<<(n5  + 255) / 256, 256>>>((const float4*)p5, n5,  valin_h + (size_t)(n3 + n4v) * 4, valin_l + (size_t)(n3 + n4v) * 4);

    const int TM = (MTOT + 127) / 128;   // 411

    // ---- value projection ----
    mma_gemm<0><<<dim3(2, TM), 256, GSMEM>>>(valin_h, valin_l, WvT, bv,
                                             val, nullptr, nullptr, MTOT, Dm, Dm);
    // ---- fused q projections (off|attn|ref) ----
    mma_gemm<0><<<dim3(3, TM), 256, GSMEM>>>(qh, ql, WqT, bq,
                                             qcat, nullptr, nullptr, MTOT, Dm, NQC);
    // ---- sampling ----
    sample_kernel<<<MTOT / 4, 256>>>(sah, sal);
    // ---- output projection + LN1 ----
    mma_gemm<0><<<dim3(2, TM), 256, GSMEM>>>(sah, sal, WoT, bo,
                                             bufB, nullptr, nullptr, MTOT, Dm, Dm);
    ln_residual<1><<<MTOT, 256>>>(query, bufB, g1, be1, qf, qnh, qnl);
    // ---- FFN ----
    mma_gemm<1><<<dim3(8, TM), 256, GSMEM>>>(qnh, qnl, W1T, b1,
                                             nullptr, h1h, h1l, MTOT, Dm, FFd);
    mma_gemm<0><<<dim3(2, TM), 256, GSMEM>>>(h1h, h1l, W2T, b2,
                                             bufB, nullptr, nullptr, MTOT, FFd, Dm);
    ln_residual<0><<<MTOT, 256>>>(qf, bufB, g2, be2, out, nullptr, nullptr);
}

// round 6
// speedup vs baseline: 5.0001x; 1.6428x over previous
#include <cuda_runtime.h>
#include <cuda_fp16.h>
#include <math.h>
#include <cstdint>

// ---------------- problem constants ----------------
#define Bsz   4
#define NTOK  13125
#define MTOT  (Bsz*NTOK)      // 52500
#define Dm    256
#define NHd   8
#define DHd   32
#define FFd   1024
#define NQC   384             // fused q-proj width: 192 off | 96 attn | 2 ref | 94 pad

__device__ __constant__ int    c_lvlH[3] = {100, 50, 25};
__device__ __constant__ int    c_lvlW[3] = {100, 50, 25};
__device__ __constant__ int    c_lvlN[3] = {10000, 2500, 625};
__device__ __constant__ size_t c_lvlOff[3] = {0, (size_t)Bsz*10000*Dm,
                                              (size_t)Bsz*10000*Dm + (size_t)Bsz*2500*Dm};

// ---------------- scratch (__device__ globals; no allocations) ----------------
__device__ __align__(16) __half g_valin [(size_t)MTOT*Dm];   // fp16 cast of p3|p4|p5
__device__ __align__(16) __half g_valh  [(size_t)MTOT*Dm];   // projected values (fp16)
__device__ __align__(16) __half g_qh    [(size_t)MTOT*Dm];   // fp16 cast of query
__device__ __align__(16) float  g_qcat  [(size_t)MTOT*NQC];  // off|attn|ref logits
__device__ __align__(16) __half g_sah   [(size_t)MTOT*Dm];   // sampled attn out (fp16)
__device__ __align__(16) float  g_bufB  [(size_t)MTOT*Dm];
__device__ __align__(16) float  g_q     [(size_t)MTOT*Dm];
__device__ __align__(16) __half g_qnh   [(size_t)MTOT*Dm];   // LN1 out (fp16)
__device__ __align__(16) __half g_h1h   [(size_t)MTOT*FFd];  // gelu(FFN hidden) (fp16)

__device__ __align__(16) __half g_WvT [Dm*Dm];
__device__ __align__(16) __half g_WqT [NQC*Dm];
__device__ __align__(16) __half g_WoT [Dm*Dm];
__device__ __align__(16) __half g_W1T [FFd*Dm];
__device__ __align__(16) __half g_W2T [Dm*FFd];
__device__ float  g_bq[NQC];

// ---------------- baseline-PTX primitives ----------------
__device__ __forceinline__ uint32_t smem_u32(const void* p) {
    uint32_t a;
    asm("{ .reg .u64 t; cvta.to.shared.u64 t, %1; cvt.u32.u64 %0, t; }" : "=r"(a) : "l"(p));
    return a;
}
__device__ __forceinline__ void cpa16(uint32_t dst, const void* src, int srcBytes) {
    asm volatile("cp.async.cg.shared.global [%0], [%1], 16, %2;"
                 :: "r"(dst), "l"(src), "r"(srcBytes) : "memory");
}
__device__ __forceinline__ void cpa_commit() {
    asm volatile("cp.async.commit_group;" ::: "memory");
}
template<int N> __device__ __forceinline__ void cpa_wait() {
    asm volatile("cp.async.wait_group %0;" :: "n"(N) : "memory");
}
__device__ __forceinline__ void ldm_x4(uint32_t& r0, uint32_t& r1, uint32_t& r2, uint32_t& r3,
                                       uint32_t addr) {
    asm volatile("ldmatrix.sync.aligned.m8n8.x4.shared.b16 {%0,%1,%2,%3}, [%4];"
                 : "=r"(r0), "=r"(r1), "=r"(r2), "=r"(r3) : "r"(addr));
}
__device__ __forceinline__ void mma_f16(float* d, const uint32_t* a, uint32_t b0, uint32_t b1) {
    asm volatile(
        "mma.sync.aligned.m16n8k16.row.col.f32.f16.f16.f32 "
        "{%0,%1,%2,%3}, {%4,%5,%6,%7}, {%8,%9}, {%0,%1,%2,%3};"
        : "+f"(d[0]), "+f"(d[1]), "+f"(d[2]), "+f"(d[3])
        : "r"(a[0]), "r"(a[1]), "r"(a[2]), "r"(a[3]), "r"(b0), "r"(b1));
}
__device__ __forceinline__ uint32_t pack_h2(float a, float b) {
    __half h0 = __float2half_rn(a), h1 = __float2half_rn(b);
    return ((uint32_t)__half_as_ushort(h1) << 16) | __half_as_ushort(h0);
}

// ---------------- HMMA GEMM: C[M,N] = A[M,K] @ BT[N,K]^T + bias ----------------
// Single fp16 term, fp32 accumulate. BM=BN=128, BK=32, 256 threads,
// warp grid 2(M)x4(N), 4-stage cp.async pipeline.
// EPI=0: fp32 out. EPI=1: exact GELU -> fp16. EPI=2: bias -> fp16.
#define ROWB   80                       // padded row pitch bytes (40 halves)
#define TILEB2 (128*ROWB)               // 10240 B per tile
#define STAGEB (2*TILEB2)               // A|B = 20480 B
#define NSTG   4
#define GSMEM  (NSTG*STAGEB)            // 81920 B

__device__ __forceinline__ void load_stage(
    int stage,
    const __half* __restrict__ A, const __half* __restrict__ B,
    int bm, int bn, int M, int K, int k0, int tid, uint32_t sb)
{
#pragma unroll
    for (int i = 0; i < 4; i++) {
        const int c    = i * 256 + tid;        // 0..1023
        const int tile = c >> 9;               // 0..1
        const int r    = (c >> 2) & 127;
        const int kc   = c & 3;
        const __half* src = (tile == 0) ? A : B;
        const int row0 = (tile == 0) ? bm : bn;
        int grow = row0 + r;
        int ok = 16;
        if (tile == 0 && grow >= M) { grow = 0; ok = 0; }
        const uint32_t dst = sb + stage * STAGEB + tile * TILEB2 + r * ROWB + kc * 16;
        cpa16(dst, src + (size_t)grow * K + k0 + kc * 8, ok);
    }
}

template<int EPI>
__global__ __launch_bounds__(256, 1)
void mma_gemm(const __half* __restrict__ A, const __half* __restrict__ B,
              const float* __restrict__ bias,
              float* __restrict__ C, __half* __restrict__ Ch,
              int M, int K, int N)
{
    extern __shared__ char smem[];
    const uint32_t sb = smem_u32(smem);
    const int tid = threadIdx.x, wid = tid >> 5, lane = tid & 31;
    const int bm = blockIdx.y * 128, bn = blockIdx.x * 128;
    const int wm = wid & 1, wn = wid >> 1;
    const int KT = K >> 5;

    float acc[4][4][4];
#pragma unroll
    for (int a = 0; a < 4; a++)
#pragma unroll
        for (int b = 0; b < 4; b++)
#pragma unroll
            for (int r = 0; r < 4; r++) acc[a][b][r] = 0.f;

    load_stage(0, A, B, bm, bn, M, K, 0,  tid, sb); cpa_commit();
    load_stage(1, A, B, bm, bn, M, K, 32, tid, sb); cpa_commit();
    load_stage(2, A, B, bm, bn, M, K, 64, tid, sb); cpa_commit();

    const int lr = lane & 15, lc = lane >> 4;

    for (int kt = 0; kt < KT; kt++) {
        if (kt + 3 < KT)
            load_stage((kt + 3) % NSTG, A, B, bm, bn, M, K, (kt + 3) * 32, tid, sb);
        cpa_commit();
        cpa_wait<3>();
        __syncthreads();

        const uint32_t st = sb + (kt % NSTG) * STAGEB;
#pragma unroll
        for (int kk = 0; kk < 2; kk++) {
            const uint32_t colo = kk * 32 + lc * 16;
            uint32_t ah[4][4], bh[2][4];
#pragma unroll
            for (int mi = 0; mi < 4; mi++) {
                const uint32_t ra = (wm * 64 + mi * 16 + lr) * ROWB + colo;
                ldm_x4(ah[mi][0], ah[mi][1], ah[mi][2], ah[mi][3], st + 0 * TILEB2 + ra);
            }
#pragma unroll
            for (int ni = 0; ni < 2; ni++) {
                const uint32_t rb = (wn * 32 + ni * 16 + lr) * ROWB + colo;
                ldm_x4(bh[ni][0], bh[ni][1], bh[ni][2], bh[ni][3], st + 1 * TILEB2 + rb);
            }
#pragma unroll
            for (int mi = 0; mi < 4; mi++)
#pragma unroll
                for (int n = 0; n < 4; n++) {
                    const int ni = n >> 1, s = n & 1;
                    mma_f16(acc[mi][n], ah[mi], bh[ni][s], bh[ni][s + 2]);
                }
        }
        __syncthreads();
    }

    // epilogue
    const int g = lane >> 2, t2 = (lane & 3) * 2;
#pragma unroll
    for (int mi = 0; mi < 4; mi++) {
        const int r0 = bm + wm * 64 + mi * 16 + g;
#pragma unroll
        for (int n = 0; n < 4; n++) {
            const int col = bn + wn * 32 + n * 8 + t2;
            const float b0 = bias[col], b1 = bias[col + 1];
#pragma unroll
            for (int h = 0; h < 2; h++) {
                const int row = r0 + h * 8;
                if (row >= M) continue;
                float v0 = acc[mi][n][2 * h + 0] + b0;
                float v1 = acc[mi][n][2 * h + 1] + b1;
                if (EPI == 0) {
                    *(float2*)(C + (size_t)row * N + col) = make_float2(v0, v1);
                } else if (EPI == 1) {
                    v0 = 0.5f * v0 * (1.f + erff(v0 * 0.70710678118654752f));
                    v1 = 0.5f * v1 * (1.f + erff(v1 * 0.70710678118654752f));
                    *(uint32_t*)(Ch + (size_t)row * N + col) = pack_h2(v0, v1);
                } else {
                    *(uint32_t*)(Ch + (size_t)row * N + col) = pack_h2(v0, v1);
                }
            }
        }
    }
}

// ---------------- prep kernels ----------------
__global__ void act_half(const float4* __restrict__ in, int n4, __half* __restrict__ h)
{
    const int i = blockIdx.x * blockDim.x + threadIdx.x;
    if (i >= n4) return;
    const float4 v = in[i];
    uint2 uh;
    uh.x = pack_h2(v.x, v.y);
    uh.y = pack_h2(v.z, v.w);
    *(uint2*)(h + (size_t)i * 4) = uh;
}

// transpose W[K,N] -> T[N,K] fp16
__global__ void wt_half(const float* __restrict__ W, int K, int N, __half* __restrict__ T)
{
    const int i = blockIdx.x * blockDim.x + threadIdx.x;
    if (i >= N * K) return;
    const int n = i / K, k = i % K;
    T[i] = __float2half_rn(W[(size_t)k * N + n]);
}

__global__ void build_bq(const float* __restrict__ boff, const float* __restrict__ battn,
                         const float* __restrict__ bref, float* __restrict__ bq,
                         __half* __restrict__ T)
{
    const int i = blockIdx.x * blockDim.x + threadIdx.x;
    if (i < NQC)
        bq[i] = (i < 192) ? boff[i] : (i < 288) ? battn[i - 192] : (i < 290) ? bref[i - 288] : 0.f;
    const int padN = (NQC - 290) * Dm;
    if (i < padN) T[290 * Dm + i] = __float2half_rn(0.f);
}

// ---------------- fused softmax + sigmoid + bilinear sampling ----------------
// 32 threads/token, 4 tokens per 128-thread block; thread = (head, 8-channel group)
__global__ __launch_bounds__(128)
void sample_kernel(__half* __restrict__ oh)
{
    const int tid  = threadIdx.x;
    const int sub  = tid >> 5;                 // token within block (0..3)
    const int t    = blockIdx.x * 4 + sub;
    const int b    = t / NTOK;
    const int tid2 = tid & 31;
    const int h    = tid2 >> 2;                // head 0..7
    const int cg   = tid2 & 3;                 // channel group (8 ch)

    __shared__ float s_aw[4][96], s_x[4][96], s_y[4][96];

    const float refx = 1.f / (1.f + __expf(-g_qcat[(size_t)t * NQC + 288]));
    const float refy = 1.f / (1.f + __expf(-g_qcat[(size_t)t * NQC + 289]));

    for (int i = tid2; i < 96; i += 32) {
        const int lp = i % 12;
        const int l  = lp >> 2;
        const float ox = g_qcat[(size_t)t * NQC + i * 2 + 0];
        const float oy = g_qcat[(size_t)t * NQC + i * 2 + 1];
        s_x[sub][i]  = fmaf(refx, (float)c_lvlW[l], ox) - 0.5f;
        s_y[sub][i]  = fmaf(refy, (float)c_lvlH[l], oy) - 0.5f;
        s_aw[sub][i] = g_qcat[(size_t)t * NQC + 192 + i];
    }
    __syncthreads();

    if (tid2 < 8) {    // per-head softmax over 12 (l,p)
        float m = -1e30f;
#pragma unroll
        for (int j = 0; j < 12; j++) m = fmaxf(m, s_aw[sub][tid2 * 12 + j]);
        float s = 0.f;
#pragma unroll
        for (int j = 0; j < 12; j++) {
            const float e = __expf(s_aw[sub][tid2 * 12 + j] - m);
            s_aw[sub][tid2 * 12 + j] = e; s += e;
        }
        const float inv = 1.f / s;
#pragma unroll
        for (int j = 0; j < 12; j++) s_aw[sub][tid2 * 12 + j] *= inv;
    }
    __syncthreads();

    float acc[8];
#pragma unroll
    for (int i = 0; i < 8; i++) acc[i] = 0.f;

#pragma unroll
    for (int l = 0; l < 3; l++) {
        const int Hl = c_lvlH[l], Wl = c_lvlW[l];
        const __half* vl = g_valh + c_lvlOff[l] + (size_t)b * c_lvlN[l] * Dm + (h * DHd + cg * 8);
#pragma unroll
        for (int p = 0; p < 4; p++) {
            const int idx = h * 12 + l * 4 + p;
            const float x = s_x[sub][idx], y = s_y[sub][idx], w = s_aw[sub][idx];
            const float x0f = floorf(x), y0f = floorf(y);
            const int x0 = (int)x0f, y0 = (int)y0f;
            const float lx = x - x0f, ly = y - y0f;
            const float w00 = w * (1.f - lx) * (1.f - ly);
            const float w01 = w * lx * (1.f - ly);
            const float w10 = w * (1.f - lx) * ly;
            const float w11 = w * lx * ly;
            const bool xin0 = (x0 >= 0) & (x0 < Wl);
            const bool xin1 = (x0 + 1 >= 0) & (x0 + 1 < Wl);
            const bool yin0 = (y0 >= 0) & (y0 < Hl);
            const bool yin1 = (y0 + 1 >= 0) & (y0 + 1 < Hl);
#define ACC8(cond, wgt, ro, co) \
            if (cond) { \
                const uint4 u = *(const uint4*)(vl + (size_t)((ro) * Wl + (co)) * Dm); \
                const __half2* hp = (const __half2*)&u; \
                _Pragma("unroll") \
                for (int q = 0; q < 4; q++) { \
                    const float2 f = __half22float2(hp[q]); \
                    acc[2*q+0] = fmaf(wgt, f.x, acc[2*q+0]); \
                    acc[2*q+1] = fmaf(wgt, f.y, acc[2*q+1]); \
                } \
            }
            ACC8(xin0 & yin0, w00, y0,     x0)
            ACC8(xin1 & yin0, w01, y0,     x0 + 1)
            ACC8(xin0 & yin1, w10, y0 + 1, x0)
            ACC8(xin1 & yin1, w11, y0 + 1, x0 + 1)
#undef ACC8
        }
    }
    uint4 o;
    o.x = pack_h2(acc[0], acc[1]);
    o.y = pack_h2(acc[2], acc[3]);
    o.z = pack_h2(acc[4], acc[5]);
    o.w = pack_h2(acc[6], acc[7]);
    *(uint4*)(oh + (size_t)t * Dm + h * DHd + cg * 8) = o;
}

// ---------------- residual + LayerNorm ----------------
template<int EMIT>
__global__ __launch_bounds__(256)
void ln_residual(const float* __restrict__ x, const float* __restrict__ y,
                 const float* __restrict__ g, const float* __restrict__ be,
                 float* __restrict__ out, __half* __restrict__ oh)
{
    const int t = blockIdx.x, tid = threadIdx.x;
    const float v = x[(size_t)t * Dm + tid] + y[(size_t)t * Dm + tid];

    __shared__ float sh[18];
    float s = v, sq = v * v;
#pragma unroll
    for (int o = 16; o; o >>= 1) {
        s  += __shfl_xor_sync(0xffffffffu, s,  o);
        sq += __shfl_xor_sync(0xffffffffu, sq, o);
    }
    const int w = tid >> 5, lane = tid & 31;
    if (lane == 0) { sh[w] = s; sh[w + 8] = sq; }
    __syncthreads();
    if (tid == 0) {
        float ts = 0.f, tq = 0.f;
#pragma unroll
        for (int i = 0; i < 8; i++) { ts += sh[i]; tq += sh[i + 8]; }
        sh[16] = ts * (1.f / Dm);
        sh[17] = tq * (1.f / Dm);
    }
    __syncthreads();
    const float mean = sh[16];
    const float var  = fmaxf(sh[17] - mean * mean, 0.f);
    const float inv  = rsqrtf(var + 1e-5f);
    const float o = (v - mean) * inv * g[tid] + be[tid];
    out[(size_t)t * Dm + tid] = o;
    if (EMIT) oh[(size_t)t * Dm + tid] = __float2half_rn(o);
}

// ---------------- host orchestration ----------------
extern "C" void kernel_launch(void* const* d_in, const int* in_sizes, int n_in,
                              void* d_out, int out_size)
{
    const float* query = (const float*)d_in[0];
    const float* p3    = (const float*)d_in[1];
    const float* p4    = (const float*)d_in[2];
    const float* p5    = (const float*)d_in[3];
    const float* Wv    = (const float*)d_in[4];
    const float* bv    = (const float*)d_in[5];
    const float* Woff  = (const float*)d_in[6];
    const float* boff  = (const float*)d_in[7];
    const float* Wattn = (const float*)d_in[8];
    const float* battn = (const float*)d_in[9];
    const float* Wref  = (const float*)d_in[10];
    const float* bref  = (const float*)d_in[11];
    const float* Wo    = (const float*)d_in[12];
    const float* bo    = (const float*)d_in[13];
    const float* W1    = (const float*)d_in[14];
    const float* b1    = (const float*)d_in[15];
    const float* W2    = (const float*)d_in[16];
    const float* b2    = (const float*)d_in[17];
    const float* g1    = (const float*)d_in[18];
    const float* be1   = (const float*)d_in[19];
    const float* g2    = (const float*)d_in[20];
    const float* be2   = (const float*)d_in[21];
    float* out = (float*)d_out;

    cudaFuncSetAttribute(mma_gemm<0>, cudaFuncAttributeMaxDynamicSharedMemorySize, GSMEM);
    cudaFuncSetAttribute(mma_gemm<1>, cudaFuncAttributeMaxDynamicSharedMemorySize, GSMEM);
    cudaFuncSetAttribute(mma_gemm<2>, cudaFuncAttributeMaxDynamicSharedMemorySize, GSMEM);

#define SYM(T, p, s) T* p; cudaGetSymbolAddress((void**)&p, s)
    SYM(__half, valin, g_valin);
    SYM(__half, valh, g_valh);
    SYM(__half, qh, g_qh);
    SYM(float, qcat, g_qcat);
    SYM(__half, sah, g_sah);
    SYM(float, bufB, g_bufB); SYM(float, qf, g_q);
    SYM(__half, qnh, g_qnh);
    SYM(__half, h1h, g_h1h);
    SYM(__half, WvT, g_WvT); SYM(__half, WqT, g_WqT);
    SYM(__half, WoT, g_WoT); SYM(__half, W1T, g_W1T); SYM(__half, W2T, g_W2T);
    SYM(float, bq, g_bq);
#undef SYM

    // ---- weight prep (fp16 transposed) ----
    wt_half<<<(Dm * Dm + 255) / 256, 256>>>(Wv, Dm, Dm, WvT);
    wt_half<<<(192 * Dm + 255) / 256, 256>>>(Woff,  Dm, 192, WqT);
    wt_half<<<(96  * Dm + 255) / 256, 256>>>(Wattn, Dm, 96,  WqT + 192 * Dm);
    wt_half<<<(2   * Dm + 255) / 256, 256>>>(Wref,  Dm, 2,   WqT + 288 * Dm);
    build_bq<<<((NQC - 290) * Dm + 255) / 256, 256>>>(boff, battn, bref, bq, WqT);
    wt_half<<<(Dm * Dm + 255) / 256, 256>>>(Wo, Dm, Dm, WoT);
    wt_half<<<(FFd * Dm + 255) / 256, 256>>>(W1, Dm, FFd, W1T);
    wt_half<<<(Dm * FFd + 255) / 256, 256>>>(W2, FFd, Dm, W2T);

    // ---- activation casts (fp16) ----
    const int nq4 = MTOT * Dm / 4;
    act_half<<<(nq4 + 255) / 256, 256>>>((const float4*)query, nq4, qh);
    const int n3 = Bsz * 10000 * Dm / 4, n4v = Bsz * 2500 * Dm / 4, n5 = Bsz * 625 * Dm / 4;
    act_half<<<(n3  + 255) / 256, 256>>>((const float4*)p3, n3,  valin);
    act_half<<<(n4v + 255) / 256, 256>>>((const float4*)p4, n4v, valin + (size_t)n3 * 4);
    act_half<<<(n5  + 255) / 256, 256>>>((const float4*)p5, n5,  valin + (size_t)(n3 + n4v) * 4);

    const int TM = (MTOT + 127) / 128;   // 411

    // ---- value projection (fp16 out) ----
    mma_gemm<2><<<dim3(2, TM), 256, GSMEM>>>(valin, WvT, bv, nullptr, valh, MTOT, Dm, Dm);
    // ---- fused q projections (off|attn|ref) ----
    mma_gemm<0><<<dim3(3, TM), 256, GSMEM>>>(qh, WqT, bq, qcat, nullptr, MTOT, Dm, NQC);
    // ---- sampling ----
    sample_kernel<<<MTOT / 4, 128>>>(sah);
    // ---- output projection + LN1 ----
    mma_gemm<0><<<dim3(2, TM), 256, GSMEM>>>(sah, WoT, bo, bufB, nullptr, MTOT, Dm, Dm);
    ln_residual<1><<<MTOT, 256>>>(query, bufB, g1, be1, qf, qnh);
    // ---- FFN ----
    mma_gemm<1><<<dim3(8, TM), 256, GSMEM>>>(qnh, W1T, b1, nullptr, h1h, MTOT, Dm, FFd);
    mma_gemm<0><<<dim3(2, TM), 256, GSMEM>>>(h1h, W2T, b2, bufB, nullptr, MTOT, FFd, Dm);
    ln_residual<0><<<MTOT, 256>>>(qf, bufB, g2, be2, out, nullptr);
}